// round 3
// baseline (speedup 1.0000x reference)
#include <cuda_runtime.h>

#define BATCH 2
#define SEQ   4096
#define DM    512
#define NH    8
#define DH    64
#define MTOT  (BATCH*SEQ)   // 8192

// Scratch: projected Q/K/V (tf32-rounded fp32 bits) in [B,H,S,Dh], attn out [B,S,D]
__device__ float g_Qp[BATCH*NH*SEQ*DH];
__device__ float g_Kp[BATCH*NH*SEQ*DH];
__device__ float g_Vp[BATCH*NH*SEQ*DH];
__device__ float g_At[BATCH*SEQ*DM];

// ---------------------------------------------------------------------------
__device__ __forceinline__ unsigned f2tf(float f) {
    unsigned u;
    asm("cvt.rna.tf32.f32 %0, %1;" : "=r"(u) : "f"(f));
    return u;
}
__device__ __forceinline__ float ex2_(float x) {
    float y;
    asm("ex2.approx.f32 %0, %1;" : "=f"(y) : "f"(x));
    return y;
}
// D += A(16x8)*B(8x8) tf32 row.col
__device__ __forceinline__ void mma_tf32(float* d, const unsigned* a,
                                         unsigned b0, unsigned b1) {
    asm volatile(
        "mma.sync.aligned.m16n8k8.row.col.f32.tf32.tf32.f32 "
        "{%0,%1,%2,%3}, {%4,%5,%6,%7}, {%8,%9}, {%0,%1,%2,%3};\n"
        : "+f"(d[0]), "+f"(d[1]), "+f"(d[2]), "+f"(d[3])
        : "r"(a[0]), "r"(a[1]), "r"(a[2]), "r"(a[3]), "r"(b0), "r"(b1));
}

// ---------------------------------------------------------------------------
// NT GEMM: C[m][n] = sum_k A[m][k]*B[n][k], N=K=512. 128x128 tile, BK=32,
// 256 threads = 8 warps (2 wm x 4 wn), warp tile 64x32.
// OSEL 0: fp32 -> C[m*512+n]; OSEL 1: tf32-round + [B,H,S,Dh] remap.
// ---------------------------------------------------------------------------
template <int OSEL>
__device__ __forceinline__ void gemm_body(const float* __restrict__ A,
                                          const float* __restrict__ B,
                                          float* __restrict__ C)
{
    __shared__ float sA[128][36];
    __shared__ float sB[128][36];

    const int tid = threadIdx.x;
    const int lane = tid & 31, wid = tid >> 5;
    const int g = lane >> 2, t = lane & 3;
    const int wm = wid & 1, wn = wid >> 1;   // wm: 64-row blk, wn: 32-col blk
    const int m0 = blockIdx.x << 7;
    const int n0 = blockIdx.y << 7;

    float acc[4][4][4];
#pragma unroll
    for (int mt = 0; mt < 4; mt++)
#pragma unroll
        for (int nt = 0; nt < 4; nt++)
#pragma unroll
            for (int c = 0; c < 4; c++) acc[mt][nt][c] = 0.f;

    for (int kb = 0; kb < 512; kb += 32) {
#pragma unroll
        for (int r = 0; r < 4; r++) {
            int j = tid + (r << 8);          // 0..1023
            int row = j >> 3;                // 0..127
            int c4  = (j & 7) << 2;          // 0..28
            float4 va = *(const float4*)(A + (size_t)(m0 + row) * 512 + kb + c4);
            float4 ta;
            ta.x = __uint_as_float(f2tf(va.x));
            ta.y = __uint_as_float(f2tf(va.y));
            ta.z = __uint_as_float(f2tf(va.z));
            ta.w = __uint_as_float(f2tf(va.w));
            *(float4*)&sA[row][c4] = ta;
            float4 vb = *(const float4*)(B + (size_t)(n0 + row) * 512 + kb + c4);
            float4 tb;
            tb.x = __uint_as_float(f2tf(vb.x));
            tb.y = __uint_as_float(f2tf(vb.y));
            tb.z = __uint_as_float(f2tf(vb.z));
            tb.w = __uint_as_float(f2tf(vb.w));
            *(float4*)&sB[row][c4] = tb;
        }
        __syncthreads();

#pragma unroll
        for (int ks = 0; ks < 4; ks++) {
            const int c = (ks << 3) + t;
            unsigned af[4][4], bf[4][2];
#pragma unroll
            for (int mt = 0; mt < 4; mt++) {
                int r = (wm << 6) + (mt << 4) + g;
                af[mt][0] = __float_as_uint(sA[r][c]);
                af[mt][1] = __float_as_uint(sA[r + 8][c]);
                af[mt][2] = __float_as_uint(sA[r][c + 4]);
                af[mt][3] = __float_as_uint(sA[r + 8][c + 4]);
            }
#pragma unroll
            for (int nt = 0; nt < 4; nt++) {
                int r = (wn << 5) + (nt << 3) + g;
                bf[nt][0] = __float_as_uint(sB[r][c]);
                bf[nt][1] = __float_as_uint(sB[r][c + 4]);
            }
#pragma unroll
            for (int mt = 0; mt < 4; mt++)
#pragma unroll
                for (int nt = 0; nt < 4; nt++)
                    mma_tf32(acc[mt][nt], af[mt], bf[nt][0], bf[nt][1]);
        }
        __syncthreads();
    }

#pragma unroll
    for (int mt = 0; mt < 4; mt++) {
#pragma unroll
        for (int nt = 0; nt < 4; nt++) {
            int m = m0 + (wm << 6) + (mt << 4) + g;
            int n = n0 + (wn << 5) + (nt << 3) + (t << 1);
#pragma unroll
            for (int rh = 0; rh < 2; rh++) {
                int mm = m + (rh << 3);
                float v0 = acc[mt][nt][rh * 2 + 0];
                float v1 = acc[mt][nt][rh * 2 + 1];
                if (OSEL == 0) {
                    C[(size_t)mm * 512 + n]     = v0;
                    C[(size_t)mm * 512 + n + 1] = v1;
                } else {
                    int b = mm >> 12, s = mm & 4095;
                    int h = n >> 6,  d = n & 63;
                    size_t base = (((size_t)(b * NH + h)) * SEQ + s) * DH + d;
                    C[base]     = __uint_as_float(f2tf(v0));
                    C[base + 1] = __uint_as_float(f2tf(v1));
                }
            }
        }
    }
}

__global__ __launch_bounds__(256, 2)
void gemm_proj(const float* __restrict__ q, const float* __restrict__ k,
               const float* __restrict__ v, const float* __restrict__ wq,
               const float* __restrict__ wk, const float* __restrict__ wv)
{
    const float* A; const float* B; float* C;
    if (blockIdx.z == 0)      { A = q; B = wq; C = g_Qp; }
    else if (blockIdx.z == 1) { A = k; B = wk; C = g_Kp; }
    else                      { A = v; B = wv; C = g_Vp; }
    gemm_body<1>(A, B, C);
}

__global__ __launch_bounds__(256, 2)
void gemm_out(const float* __restrict__ wo, float* __restrict__ out)
{
    gemm_body<0>(g_At, wo, out);
}

// ---------------------------------------------------------------------------
// Flash attention, tf32 mma. BQ=128, BK=64, 128 threads = 4 warps,
// warp tile 32 q-rows (2 sub-blocks of 16). Fragment-order smem layouts:
//   Kf[(nt*4+ks2)*32 + lane] (f4) = {b0(2ks2), b1(2ks2), b0(2ks2+1), b1(2ks2+1)}
//   Vf[(nt*4+k2 )*32 + lane] (f4) = V rows {16k2+t, +4, +8, +12}, col 8nt+g
//   P per-warp: Pf[(sb*8+ks)*32 + lane] (f4) = a-frag order
// smem floats: Kf 4096 | Vf 4096 | Qs(128x68, reused as P) 8704  -> 67584 B
// ---------------------------------------------------------------------------
__global__ __launch_bounds__(128, 2)
void flash_tc()
{
    extern __shared__ float sm[];
    float* Kf = sm;
    float* Vf = sm + 4096;
    float* Qs = sm + 8192;               // 128 x 68 staging

    const int tid = threadIdx.x;
    const int lane = tid & 31, w = tid >> 5;
    const int g = lane >> 2, t = lane & 3;
    const int qb = (int)(gridDim.x - 1) - (int)blockIdx.x;  // heavy first
    const int q0 = qb << 7;
    const int bh = blockIdx.y;

    const float* Qb = g_Qp + (size_t)bh * SEQ * DH;
    const float* Kb = g_Kp + (size_t)bh * SEQ * DH;
    const float* Vb = g_Vp + (size_t)bh * SEQ * DH;

    // stage Q tile 128x64 (plain, stride 68)
#pragma unroll
    for (int r = 0; r < 16; r++) {
        int j = tid + (r << 7);          // 0..2047
        int row = j >> 4, c4 = (j & 15) << 2;
        *(float4*)&Qs[row * 68 + c4] =
            *(const float4*)(Qb + (size_t)(q0 + row) * DH + c4);
    }
    __syncthreads();

    // Q a-frags, register resident. sb0 rows [32w,32w+16), sb1 +16.
    unsigned qf0[8][4], qf1[8][4];
    {
        int ra = (w << 5) + g;
#pragma unroll
        for (int ks = 0; ks < 8; ks++) {
            int c = (ks << 3) + t;
            qf0[ks][0] = __float_as_uint(Qs[ra * 68 + c]);
            qf0[ks][1] = __float_as_uint(Qs[(ra + 8) * 68 + c]);
            qf0[ks][2] = __float_as_uint(Qs[ra * 68 + c + 4]);
            qf0[ks][3] = __float_as_uint(Qs[(ra + 8) * 68 + c + 4]);
            qf1[ks][0] = __float_as_uint(Qs[(ra + 16) * 68 + c]);
            qf1[ks][1] = __float_as_uint(Qs[(ra + 24) * 68 + c]);
            qf1[ks][2] = __float_as_uint(Qs[(ra + 16) * 68 + c + 4]);
            qf1[ks][3] = __float_as_uint(Qs[(ra + 24) * 68 + c + 4]);
        }
    }

    float o0[8][4], o1[8][4];
#pragma unroll
    for (int nt = 0; nt < 8; nt++)
#pragma unroll
        for (int c = 0; c < 4; c++) { o0[nt][c] = 0.f; o1[nt][c] = 0.f; }
    float mr[4] = {-1e30f, -1e30f, -1e30f, -1e30f};  // sb0r0, sb0r1, sb1r0, sb1r1
    float lr[4] = {0.f, 0.f, 0.f, 0.f};

    const float cscale = 0.125f * 1.4426950408889634f;
    float* Pw = Qs + (w << 11);          // per-warp 2048 floats (512 f4)
    const float4* Kf4 = (const float4*)Kf;
    const float4* Vf4 = (const float4*)Vf;
    const float4* Pf4 = (const float4*)Pw;

    const int ktmax = 2 * qb + 1;
    for (int kt = 0; kt <= ktmax; kt++) {
        __syncthreads();                 // prior Kf/Vf/P reads complete
        {   // stage K and V into fragment-order layouts
            const int k0 = kt << 6;
#pragma unroll
            for (int r = 0; r < 8; r++) {
                int j = tid + (r << 7);          // 0..1023
                int row = j >> 4, ci = j & 15;   // ci: col/4
                float4 vk = *(const float4*)(Kb + (size_t)(k0 + row) * DH + (ci << 2));
                int f4b = (((row >> 3) << 2) + (ci >> 2)) * 32 + ((row & 7) << 2);
                int e = ci & 3;
                Kf[((f4b + 0) << 2) + e] = vk.x;
                Kf[((f4b + 1) << 2) + e] = vk.y;
                Kf[((f4b + 2) << 2) + e] = vk.z;
                Kf[((f4b + 3) << 2) + e] = vk.w;
                float4 vv = *(const float4*)(Vb + (size_t)(k0 + row) * DH + (ci << 2));
                int nt = ci >> 1;
                int gb = (ci << 2) & 7;
                int vb0 = ((nt << 2) + (row >> 4)) * 32 + (row & 3);
                int ev = (row & 15) >> 2;
                Vf[((vb0 + ((gb + 0) << 2)) << 2) + ev] = vv.x;
                Vf[((vb0 + ((gb + 1) << 2)) << 2) + ev] = vv.y;
                Vf[((vb0 + ((gb + 2) << 2)) << 2) + ev] = vv.z;
                Vf[((vb0 + ((gb + 3) << 2)) << 2) + ev] = vv.w;
            }
        }
        __syncthreads();

        // ---- S = Q K^T (both sub-blocks share K fragment loads) ----
        float s0[8][4], s1[8][4];
#pragma unroll
        for (int nt = 0; nt < 8; nt++)
#pragma unroll
            for (int c = 0; c < 4; c++) { s0[nt][c] = 0.f; s1[nt][c] = 0.f; }
#pragma unroll
        for (int nt = 0; nt < 8; nt++) {
#pragma unroll
            for (int ks2 = 0; ks2 < 4; ks2++) {
                float4 kb = Kf4[((nt << 2) + ks2) * 32 + lane];
                unsigned b0 = __float_as_uint(kb.x), b1 = __float_as_uint(kb.y);
                unsigned b2 = __float_as_uint(kb.z), b3 = __float_as_uint(kb.w);
                mma_tf32(s0[nt], qf0[2 * ks2],     b0, b1);
                mma_tf32(s0[nt], qf0[2 * ks2 + 1], b2, b3);
                mma_tf32(s1[nt], qf1[2 * ks2],     b0, b1);
                mma_tf32(s1[nt], qf1[2 * ks2 + 1], b2, b3);
            }
        }

        // ---- scale + causal mask ----
#pragma unroll
        for (int nt = 0; nt < 8; nt++)
#pragma unroll
            for (int c = 0; c < 4; c++) { s0[nt][c] *= cscale; s1[nt][c] *= cscale; }
        if (kt >= 2 * qb) {
            const int kvb = kt << 6;
            const int qg0 = q0 + (w << 5) + g;        // sb0 r0
#pragma unroll
            for (int nt = 0; nt < 8; nt++) {
                int kv = kvb + (nt << 3) + (t << 1);
                if (kv > qg0)          s0[nt][0] = -1e30f;
                if (kv + 1 > qg0)      s0[nt][1] = -1e30f;
                if (kv > qg0 + 8)      s0[nt][2] = -1e30f;
                if (kv + 1 > qg0 + 8)  s0[nt][3] = -1e30f;
                if (kv > qg0 + 16)     s1[nt][0] = -1e30f;
                if (kv + 1 > qg0 + 16) s1[nt][1] = -1e30f;
                if (kv > qg0 + 24)     s1[nt][2] = -1e30f;
                if (kv + 1 > qg0 + 24) s1[nt][3] = -1e30f;
            }
        }

        // ---- online softmax (4 row-sets: sb*2 + rhalf) ----
#pragma unroll
        for (int sb = 0; sb < 2; sb++) {
            float (*s)[4] = sb ? s1 : s0;
            float (*o)[4] = sb ? o1 : o0;
#pragma unroll
            for (int r = 0; r < 2; r++) {
                int ix = sb * 2 + r;
                float mx = -1e30f;
#pragma unroll
                for (int nt = 0; nt < 8; nt++)
                    mx = fmaxf(mx, fmaxf(s[nt][2 * r], s[nt][2 * r + 1]));
                mx = fmaxf(mx, __shfl_xor_sync(0xffffffffu, mx, 1));
                mx = fmaxf(mx, __shfl_xor_sync(0xffffffffu, mx, 2));
                float mn = fmaxf(mr[ix], mx);
                float al = ex2_(mr[ix] - mn);
                mr[ix] = mn;
                float rs = 0.f;
#pragma unroll
                for (int nt = 0; nt < 8; nt++) {
                    float p0 = ex2_(s[nt][2 * r] - mn);
                    float p1 = ex2_(s[nt][2 * r + 1] - mn);
                    s[nt][2 * r] = p0; s[nt][2 * r + 1] = p1;
                    rs += p0 + p1;
                }
                rs += __shfl_xor_sync(0xffffffffu, rs, 1);
                rs += __shfl_xor_sync(0xffffffffu, rs, 2);
                lr[ix] = lr[ix] * al + rs;
#pragma unroll
                for (int nt = 0; nt < 8; nt++) {
                    o[nt][2 * r]     *= al;
                    o[nt][2 * r + 1] *= al;
                }
            }
        }

        // ---- store P in a-frag order (per-warp region) ----
        {
            const int off = (t < 2) ? (t << 1) : ((t << 1) - 4);
            const int eo  = (t < 2) ? 0 : 2;
            const int gb  = (g << 2) + off;
#pragma unroll
            for (int sb = 0; sb < 2; sb++) {
                float (*s)[4] = sb ? s1 : s0;
#pragma unroll
                for (int nt = 0; nt < 8; nt++) {
                    int fb = (((sb << 3) + nt) << 5) + gb;     // f4 index
                    float* p = Pw + (fb << 2) + eo;
                    p[0] = __uint_as_float(f2tf(s[nt][0]));
                    p[4] = __uint_as_float(f2tf(s[nt][1]));
                    p[1] = __uint_as_float(f2tf(s[nt][2]));
                    p[5] = __uint_as_float(f2tf(s[nt][3]));
                }
            }
        }
        __syncwarp();

        // ---- O += P V (both sub-blocks share V fragment loads) ----
#pragma unroll
        for (int k2 = 0; k2 < 4; k2++) {
            float4 pa0 = Pf4[((2 * k2) << 5) + lane];
            float4 pa1 = Pf4[((2 * k2 + 1) << 5) + lane];
            float4 pb0 = Pf4[((8 + 2 * k2) << 5) + lane];
            float4 pb1 = Pf4[((8 + 2 * k2 + 1) << 5) + lane];
            unsigned a00[4] = {__float_as_uint(pa0.x), __float_as_uint(pa0.y),
                               __float_as_uint(pa0.z), __float_as_uint(pa0.w)};
            unsigned a01[4] = {__float_as_uint(pa1.x), __float_as_uint(pa1.y),
                               __float_as_uint(pa1.z), __float_as_uint(pa1.w)};
            unsigned a10[4] = {__float_as_uint(pb0.x), __float_as_uint(pb0.y),
                               __float_as_uint(pb0.z), __float_as_uint(pb0.w)};
            unsigned a11[4] = {__float_as_uint(pb1.x), __float_as_uint(pb1.y),
                               __float_as_uint(pb1.z), __float_as_uint(pb1.w)};
#pragma unroll
            for (int nt = 0; nt < 8; nt++) {
                float4 vb = Vf4[((nt << 2) + k2) * 32 + lane];
                unsigned v0 = __float_as_uint(vb.x), v1 = __float_as_uint(vb.y);
                unsigned v2 = __float_as_uint(vb.z), v3 = __float_as_uint(vb.w);
                mma_tf32(o0[nt], a00, v0, v1);
                mma_tf32(o0[nt], a01, v2, v3);
                mma_tf32(o1[nt], a10, v0, v1);
                mma_tf32(o1[nt], a11, v2, v3);
            }
        }
    }

    // ---- epilogue -> g_At [B, S, H*Dh] ----
    const int b = bh >> 3, h = bh & 7;
#pragma unroll
    for (int sb = 0; sb < 2; sb++) {
        float (*o)[4] = sb ? o1 : o0;
#pragma unroll
        for (int r = 0; r < 2; r++) {
            int row = q0 + (w << 5) + (sb << 4) + (r << 3) + g;
            float inv = 1.f / lr[sb * 2 + r];
#pragma unroll
            for (int nt = 0; nt < 8; nt++) {
                int col = (h << 6) + (nt << 3) + (t << 1);
                size_t base = ((size_t)b * SEQ + row) * DM + col;
                float2 v = make_float2(o[nt][2 * r] * inv, o[nt][2 * r + 1] * inv);
                *(float2*)&g_At[base] = v;
            }
        }
    }
}

// ---------------------------------------------------------------------------
extern "C" void kernel_launch(void* const* d_in, const int* in_sizes, int n_in,
                              void* d_out, int out_size)
{
    const float* q  = (const float*)d_in[0];
    const float* k  = (const float*)d_in[1];
    const float* v  = (const float*)d_in[2];
    const float* wq = (const float*)d_in[3];
    const float* wk = (const float*)d_in[4];
    const float* wv = (const float*)d_in[5];
    const float* wo = (const float*)d_in[6];
    float* out = (float*)d_out;

    const int FLASH_SMEM = (4096 + 4096 + 128 * 68) * (int)sizeof(float); // 67584
    cudaFuncSetAttribute(flash_tc, cudaFuncAttributeMaxDynamicSharedMemorySize,
                         FLASH_SMEM);

    dim3 pg(MTOT / 128, DM / 128, 3);        // 64 x 4 x 3
    gemm_proj<<<pg, 256>>>(q, k, v, wq, wk, wv);

    dim3 fg(SEQ / 128, BATCH * NH);          // 32 x 16
    flash_tc<<<fg, 128, FLASH_SMEM>>>();

    dim3 og(MTOT / 128, DM / 128);           // 64 x 4
    gemm_out<<<og, 256>>>(wo, out);
}

// round 4
// speedup vs baseline: 1.3459x; 1.3459x over previous
#include <cuda_runtime.h>

#define BATCH 2
#define SEQ   4096
#define DM    512
#define NH    8
#define DH    64
#define MTOT  (BATCH*SEQ)   // 8192

// Scratch: projected Q/K/V (tf32-rounded fp32 bits) in [B,H,S,Dh], attn out [B,S,D]
__device__ float g_Qp[BATCH*NH*SEQ*DH];
__device__ float g_Kp[BATCH*NH*SEQ*DH];
__device__ float g_Vp[BATCH*NH*SEQ*DH];
__device__ float g_At[BATCH*SEQ*DM];

// ---------------------------------------------------------------------------
__device__ __forceinline__ unsigned f2tf(float f) {
    unsigned u;
    asm("cvt.rna.tf32.f32 %0, %1;" : "=r"(u) : "f"(f));
    return u;
}
__device__ __forceinline__ float ex2_(float x) {
    float y;
    asm("ex2.approx.f32 %0, %1;" : "=f"(y) : "f"(x));
    return y;
}
// D += A(16x8)*B(8x8) tf32 row.col
__device__ __forceinline__ void mma_tf32(float* d, const unsigned* a,
                                         unsigned b0, unsigned b1) {
    asm volatile(
        "mma.sync.aligned.m16n8k8.row.col.f32.tf32.tf32.f32 "
        "{%0,%1,%2,%3}, {%4,%5,%6,%7}, {%8,%9}, {%0,%1,%2,%3};\n"
        : "+f"(d[0]), "+f"(d[1]), "+f"(d[2]), "+f"(d[3])
        : "r"(a[0]), "r"(a[1]), "r"(a[2]), "r"(a[3]), "r"(b0), "r"(b1));
}

// ---------------------------------------------------------------------------
// NT GEMM (Round-2 config, measured fastest): C[m][n] = sum_k A[m][k]*B[n][k],
// N=K=512. 128x128 tile, BK=32, 128 threads = 4 warps (2x2), warp tile 64x64.
// OSEL 0: fp32 -> C[m*512+n]; OSEL 1: tf32-round + [B,H,S,Dh] remap.
// ---------------------------------------------------------------------------
template <int OSEL>
__device__ __forceinline__ void gemm_body(const float* __restrict__ A,
                                          const float* __restrict__ B,
                                          float* __restrict__ C)
{
    __shared__ float sA[128][36];
    __shared__ float sB[128][36];

    const int tid = threadIdx.x;
    const int lane = tid & 31, wid = tid >> 5;
    const int g = lane >> 2, t = lane & 3;
    const int wm = wid & 1, wn = wid >> 1;          // 2x2 warp grid
    const int m0 = blockIdx.x << 7;
    const int n0 = blockIdx.y << 7;

    float acc[4][8][4];
#pragma unroll
    for (int mt = 0; mt < 4; mt++)
#pragma unroll
        for (int nt = 0; nt < 8; nt++)
#pragma unroll
            for (int c = 0; c < 4; c++) acc[mt][nt][c] = 0.f;

    const int r0 = tid >> 3;            // 0..15
    const int c4 = (tid & 7) << 2;      // 0..28 step 4

    for (int kb = 0; kb < 512; kb += 32) {
#pragma unroll
        for (int rr = 0; rr < 8; rr++) {
            int row = r0 + (rr << 4);
            float4 va = *(const float4*)(A + (size_t)(m0 + row) * 512 + kb + c4);
            float4 ta;
            ta.x = __uint_as_float(f2tf(va.x));
            ta.y = __uint_as_float(f2tf(va.y));
            ta.z = __uint_as_float(f2tf(va.z));
            ta.w = __uint_as_float(f2tf(va.w));
            *(float4*)&sA[row][c4] = ta;
            float4 vb = *(const float4*)(B + (size_t)(n0 + row) * 512 + kb + c4);
            float4 tb;
            tb.x = __uint_as_float(f2tf(vb.x));
            tb.y = __uint_as_float(f2tf(vb.y));
            tb.z = __uint_as_float(f2tf(vb.z));
            tb.w = __uint_as_float(f2tf(vb.w));
            *(float4*)&sB[row][c4] = tb;
        }
        __syncthreads();

#pragma unroll
        for (int ks = 0; ks < 4; ks++) {
            unsigned af[4][4], bf[8][2];
#pragma unroll
            for (int mt = 0; mt < 4; mt++) {
                int r = (wm << 6) + (mt << 4) + g;
                int c = (ks << 3) + t;
                af[mt][0] = __float_as_uint(sA[r][c]);
                af[mt][1] = __float_as_uint(sA[r + 8][c]);
                af[mt][2] = __float_as_uint(sA[r][c + 4]);
                af[mt][3] = __float_as_uint(sA[r + 8][c + 4]);
            }
#pragma unroll
            for (int nt = 0; nt < 8; nt++) {
                int r = (wn << 6) + (nt << 3) + g;
                int c = (ks << 3) + t;
                bf[nt][0] = __float_as_uint(sB[r][c]);
                bf[nt][1] = __float_as_uint(sB[r][c + 4]);
            }
#pragma unroll
            for (int mt = 0; mt < 4; mt++)
#pragma unroll
                for (int nt = 0; nt < 8; nt++)
                    mma_tf32(acc[mt][nt], af[mt], bf[nt][0], bf[nt][1]);
        }
        __syncthreads();
    }

#pragma unroll
    for (int mt = 0; mt < 4; mt++) {
#pragma unroll
        for (int nt = 0; nt < 8; nt++) {
            int m = m0 + (wm << 6) + (mt << 4) + g;
            int n = n0 + (wn << 6) + (nt << 3) + (t << 1);
#pragma unroll
            for (int rh = 0; rh < 2; rh++) {
                int mm = m + (rh << 3);
                float v0 = acc[mt][nt][rh * 2 + 0];
                float v1 = acc[mt][nt][rh * 2 + 1];
                if (OSEL == 0) {
                    C[(size_t)mm * 512 + n]     = v0;
                    C[(size_t)mm * 512 + n + 1] = v1;
                } else {
                    int b = mm >> 12, s = mm & 4095;
                    int h = n >> 6,  d = n & 63;
                    size_t base = (((size_t)(b * NH + h)) * SEQ + s) * DH + d;
                    C[base]     = __uint_as_float(f2tf(v0));
                    C[base + 1] = __uint_as_float(f2tf(v1));
                }
            }
        }
    }
}

__global__ __launch_bounds__(128, 2)
void gemm_proj(const float* __restrict__ q, const float* __restrict__ k,
               const float* __restrict__ v, const float* __restrict__ wq,
               const float* __restrict__ wk, const float* __restrict__ wv)
{
    const float* A; const float* B; float* C;
    if (blockIdx.z == 0)      { A = q; B = wq; C = g_Qp; }
    else if (blockIdx.z == 1) { A = k; B = wk; C = g_Kp; }
    else                      { A = v; B = wv; C = g_Vp; }
    gemm_body<1>(A, B, C);
}

__global__ __launch_bounds__(128, 2)
void gemm_out(const float* __restrict__ wo, float* __restrict__ out)
{
    gemm_body<0>(g_At, wo, out);
}

// ---------------------------------------------------------------------------
// Flash attention, tf32 mma. BQ=128, BK=64, 128 threads = 4 warps,
// warp = 32 q-rows (2 sub-blocks of 16), ks-OUTER loops so only 8 Q/P regs
// are live at a time while each K/V b-frag feeds 2 mmas.
// smem (floats, plain padded layouts):
//   Qs [128][68]  persistent Q tile        (offset 0)
//   Ps [128][68]  P tiles, warp w rows 32w (offset 8704)
//   sK [64][68]                            (offset 17408)
//   sV [64][72]   (stride 72: conflict-free V b-frag loads)
// total 26368 floats = 105472 B -> 2 CTA/SM.
// ---------------------------------------------------------------------------
__global__ __launch_bounds__(128, 2)
void flash_tc()
{
    extern __shared__ float sm[];
    float* Qs = sm;
    float* Ps = sm + 8704;
    float* sK = sm + 17408;
    float* sV = sm + 21760;

    const int tid = threadIdx.x;
    const int lane = tid & 31, w = tid >> 5;
    const int g = lane >> 2, t = lane & 3;
    const int qb = (int)(gridDim.x - 1) - (int)blockIdx.x;  // heavy tiles first
    const int q0 = qb << 7;
    const int bh = blockIdx.y;

    const float* Qb = g_Qp + (size_t)bh * SEQ * DH;
    const float* Kb = g_Kp + (size_t)bh * SEQ * DH;
    const float* Vb = g_Vp + (size_t)bh * SEQ * DH;

    // stage Q tile 128x64 into Qs (persistent)
#pragma unroll
    for (int r = 0; r < 16; r++) {
        int j = tid + (r << 7);
        int row = j >> 4, c4 = (j & 15) << 2;
        *(float4*)&Qs[row * 68 + c4] =
            *(const float4*)(Qb + (size_t)(q0 + row) * DH + c4);
    }

    float o0[8][4], o1[8][4];
#pragma unroll
    for (int nt = 0; nt < 8; nt++)
#pragma unroll
        for (int c = 0; c < 4; c++) { o0[nt][c] = 0.f; o1[nt][c] = 0.f; }
    float mr[4] = {-1e30f, -1e30f, -1e30f, -1e30f};
    float lr[4] = {0.f, 0.f, 0.f, 0.f};

    const float cscale = 0.125f * 1.4426950408889634f;  // 1/sqrt(64) * log2(e)
    const int rw = w << 5;                 // warp's base q-row (local)
    const int qrow = rw + g;               // a-frag row (sb0, r0)

    const int ktmax = 2 * qb + 1;
    for (int kt = 0; kt <= ktmax; kt++) {
        __syncthreads();                   // prior sK/sV reads done (also Q stage)
        {   // stage K, V tiles (64x64 each)
            const int k0 = kt << 6;
#pragma unroll
            for (int r = 0; r < 8; r++) {
                int j = tid + (r << 7);
                int row = j >> 4, c4 = (j & 15) << 2;
                *(float4*)&sK[row * 68 + c4] =
                    *(const float4*)(Kb + (size_t)(k0 + row) * DH + c4);
                *(float4*)&sV[row * 72 + c4] =
                    *(const float4*)(Vb + (size_t)(k0 + row) * DH + c4);
            }
        }
        __syncthreads();

        // ---- S = Q K^T : ks outer (8 live Q regs), b-frags shared by 2 sb ----
        float s0[8][4], s1[8][4];
#pragma unroll
        for (int nt = 0; nt < 8; nt++)
#pragma unroll
            for (int c = 0; c < 4; c++) { s0[nt][c] = 0.f; s1[nt][c] = 0.f; }
#pragma unroll
        for (int ks = 0; ks < 8; ks++) {
            const int c = (ks << 3) + t;
            unsigned qf0[4], qf1[4];
            qf0[0] = __float_as_uint(Qs[(qrow)      * 68 + c]);
            qf0[1] = __float_as_uint(Qs[(qrow + 8)  * 68 + c]);
            qf0[2] = __float_as_uint(Qs[(qrow)      * 68 + c + 4]);
            qf0[3] = __float_as_uint(Qs[(qrow + 8)  * 68 + c + 4]);
            qf1[0] = __float_as_uint(Qs[(qrow + 16) * 68 + c]);
            qf1[1] = __float_as_uint(Qs[(qrow + 24) * 68 + c]);
            qf1[2] = __float_as_uint(Qs[(qrow + 16) * 68 + c + 4]);
            qf1[3] = __float_as_uint(Qs[(qrow + 24) * 68 + c + 4]);
#pragma unroll
            for (int nt = 0; nt < 8; nt++) {
                int r = (nt << 3) + g;
                unsigned b0 = __float_as_uint(sK[r * 68 + c]);
                unsigned b1 = __float_as_uint(sK[r * 68 + c + 4]);
                mma_tf32(s0[nt], qf0, b0, b1);
                mma_tf32(s1[nt], qf1, b0, b1);
            }
        }

        // ---- scale + causal mask (only on the two diagonal-spanning tiles) --
#pragma unroll
        for (int nt = 0; nt < 8; nt++)
#pragma unroll
            for (int c = 0; c < 4; c++) { s0[nt][c] *= cscale; s1[nt][c] *= cscale; }
        if (kt >= 2 * qb) {
            const int kvb = kt << 6;
            const int qg0 = q0 + qrow;
#pragma unroll
            for (int nt = 0; nt < 8; nt++) {
                int kv = kvb + (nt << 3) + (t << 1);
                if (kv > qg0)          s0[nt][0] = -1e30f;
                if (kv + 1 > qg0)      s0[nt][1] = -1e30f;
                if (kv > qg0 + 8)      s0[nt][2] = -1e30f;
                if (kv + 1 > qg0 + 8)  s0[nt][3] = -1e30f;
                if (kv > qg0 + 16)     s1[nt][0] = -1e30f;
                if (kv + 1 > qg0 + 16) s1[nt][1] = -1e30f;
                if (kv > qg0 + 24)     s1[nt][2] = -1e30f;
                if (kv + 1 > qg0 + 24) s1[nt][3] = -1e30f;
            }
        }

        // ---- online softmax (4 row-sets) ----
#pragma unroll
        for (int sb = 0; sb < 2; sb++) {
            float (*s)[4] = sb ? s1 : s0;
            float (*o)[4] = sb ? o1 : o0;
#pragma unroll
            for (int r = 0; r < 2; r++) {
                int ix = sb * 2 + r;
                float mx = -1e30f;
#pragma unroll
                for (int nt = 0; nt < 8; nt++)
                    mx = fmaxf(mx, fmaxf(s[nt][2 * r], s[nt][2 * r + 1]));
                mx = fmaxf(mx, __shfl_xor_sync(0xffffffffu, mx, 1));
                mx = fmaxf(mx, __shfl_xor_sync(0xffffffffu, mx, 2));
                float mn = fmaxf(mr[ix], mx);
                float al = ex2_(mr[ix] - mn);
                mr[ix] = mn;
                float rs = 0.f;
#pragma unroll
                for (int nt = 0; nt < 8; nt++) {
                    float p0 = ex2_(s[nt][2 * r] - mn);
                    float p1 = ex2_(s[nt][2 * r + 1] - mn);
                    s[nt][2 * r] = p0; s[nt][2 * r + 1] = p1;
                    rs += p0 + p1;
                }
                rs += __shfl_xor_sync(0xffffffffu, rs, 1);
                rs += __shfl_xor_sync(0xffffffffu, rs, 2);
                lr[ix] = lr[ix] * al + rs;
#pragma unroll
                for (int nt = 0; nt < 8; nt++) {
                    o[nt][2 * r]     *= al;
                    o[nt][2 * r + 1] *= al;
                }
            }
        }

        // ---- store P (tf32) to warp-private Ps rows, c-frag layout ----
#pragma unroll
        for (int sb = 0; sb < 2; sb++) {
            float (*s)[4] = sb ? s1 : s0;
            int rbase = rw + (sb << 4) + g;
#pragma unroll
            for (int nt = 0; nt < 8; nt++) {
                int col = (nt << 3) + (t << 1);
                float2 lo = make_float2(__uint_as_float(f2tf(s[nt][0])),
                                        __uint_as_float(f2tf(s[nt][1])));
                float2 hi = make_float2(__uint_as_float(f2tf(s[nt][2])),
                                        __uint_as_float(f2tf(s[nt][3])));
                *(float2*)&Ps[rbase * 68 + col]       = lo;
                *(float2*)&Ps[(rbase + 8) * 68 + col] = hi;
            }
        }
        __syncwarp();

        // ---- O += P V : ks outer, V b-frags shared by 2 sb ----
#pragma unroll
        for (int ks = 0; ks < 8; ks++) {
            const int c = (ks << 3) + t;
            unsigned pf0[4], pf1[4];
            pf0[0] = __float_as_uint(Ps[(qrow)      * 68 + c]);
            pf0[1] = __float_as_uint(Ps[(qrow + 8)  * 68 + c]);
            pf0[2] = __float_as_uint(Ps[(qrow)      * 68 + c + 4]);
            pf0[3] = __float_as_uint(Ps[(qrow + 8)  * 68 + c + 4]);
            pf1[0] = __float_as_uint(Ps[(qrow + 16) * 68 + c]);
            pf1[1] = __float_as_uint(Ps[(qrow + 24) * 68 + c]);
            pf1[2] = __float_as_uint(Ps[(qrow + 16) * 68 + c + 4]);
            pf1[3] = __float_as_uint(Ps[(qrow + 24) * 68 + c + 4]);
            const int kr = (ks << 3) + t;
#pragma unroll
            for (int nt = 0; nt < 8; nt++) {
                int nc = (nt << 3) + g;
                unsigned v0 = __float_as_uint(sV[kr * 72 + nc]);
                unsigned v1 = __float_as_uint(sV[(kr + 4) * 72 + nc]);
                mma_tf32(o0[nt], pf0, v0, v1);
                mma_tf32(o1[nt], pf1, v0, v1);
            }
        }
    }

    // ---- epilogue -> g_At [B, S, H*Dh] ----
    const int b = bh >> 3, h = bh & 7;
#pragma unroll
    for (int sb = 0; sb < 2; sb++) {
        float (*o)[4] = sb ? o1 : o0;
#pragma unroll
        for (int r = 0; r < 2; r++) {
            int row = q0 + rw + (sb << 4) + (r << 3) + g;
            float inv = 1.f / lr[sb * 2 + r];
#pragma unroll
            for (int nt = 0; nt < 8; nt++) {
                int col = (h << 6) + (nt << 3) + (t << 1);
                size_t base = ((size_t)b * SEQ + row) * DM + col;
                float2 v = make_float2(o[nt][2 * r] * inv, o[nt][2 * r + 1] * inv);
                *(float2*)&g_At[base] = v;
            }
        }
    }
}

// ---------------------------------------------------------------------------
extern "C" void kernel_launch(void* const* d_in, const int* in_sizes, int n_in,
                              void* d_out, int out_size)
{
    const float* q  = (const float*)d_in[0];
    const float* k  = (const float*)d_in[1];
    const float* v  = (const float*)d_in[2];
    const float* wq = (const float*)d_in[3];
    const float* wk = (const float*)d_in[4];
    const float* wv = (const float*)d_in[5];
    const float* wo = (const float*)d_in[6];
    float* out = (float*)d_out;

    const int FLASH_SMEM = (8704 + 8704 + 4352 + 4608) * (int)sizeof(float); // 105472
    cudaFuncSetAttribute(flash_tc, cudaFuncAttributeMaxDynamicSharedMemorySize,
                         FLASH_SMEM);

    dim3 pg(MTOT / 128, DM / 128, 3);        // 64 x 4 x 3
    gemm_proj<<<pg, 128>>>(q, k, v, wq, wk, wv);

    dim3 fg(SEQ / 128, BATCH * NH);          // 32 x 16
    flash_tc<<<fg, 128, FLASH_SMEM>>>();

    dim3 og(MTOT / 128, DM / 128);           // 64 x 4
    gemm_out<<<og, 128>>>(wo, out);
}